// round 17
// baseline (speedup 1.0000x reference)
#include <cuda_runtime.h>
#include <cuda_fp16.h>
#include <math.h>
#include <stdint.h>

// ===========================================================================
// B=4096, S=128, A=32, H=1024, N=256.
// ldmatrix + mma.sync.m16n8k16 + cp.async (base PTX, compute_103-safe).
// Precision plan (frozen): L1+loc merged (3-term), L4 (3-term),
//   L2/L3 (1-term), expert (1-term).
// This round: STREAM OVERLAP — expert GEMM runs concurrently with the
// L2->L3->L4 chain (fork/join via events; capturable). L2/L3 re-plumbed
// through the dead g_wel plane so the expert's read of a1 never races.
// ===========================================================================

#define SWZ(o) ((o) ^ (((o) >> 3) & 0x70))

// ---------------- device scratch (allocation-free rule) --------------------
__device__ __half g_a0h[4096 * 1024];
__device__ __half g_a0l[4096 * 1024];
__device__ __half g_a1h[4096 * 1024];
__device__ __half g_a1l[4096 * 1024];
__device__ __half g_sh[4096 * 128];
__device__ __half g_sl[4096 * 128];
__device__ __half g_w1h[1024 * 128];
__device__ __half g_w1l[1024 * 128];
__device__ __half g_w2h[1024 * 1024];
__device__ __half g_w2l[1024 * 1024];
__device__ __half g_w3h[1024 * 1024];
__device__ __half g_w3l[1024 * 1024];
__device__ __half g_w4h[256 * 1024];
__device__ __half g_w4l[256 * 1024];
__device__ __half g_wlh[1024 * 128];
__device__ __half g_wll[1024 * 128];
__device__ __half g_weh[8192 * 1024];
__device__ __half g_wel[8192 * 1024];   // dead as weights; reused as L2 output
__device__ float g_values[4096 * 256];
__device__ float g_dist[4096 * 256];

__device__ __forceinline__ void* sp(int id) {
    switch (id) {
        case 0:  return g_a0h; case 1:  return g_a0l;
        case 2:  return g_a1h; case 3:  return g_a1l;
        case 4:  return g_sh;  case 5:  return g_sl;
        case 6:  return g_w1h; case 7:  return g_w1l;
        case 8:  return g_w2h; case 9:  return g_w2l;
        case 10: return g_w3h; case 11: return g_w3l;
        case 12: return g_w4h; case 13: return g_w4l;
        case 14: return g_wlh; case 15: return g_wll;
        case 16: return g_weh; case 17: return g_wel;
        case 18: return g_values;
        case 19: return g_dist;
        default: return g_wel + 4096 * 1024;   // id 20: upper half of g_wel
    }
}

// ---------------- PTX helpers (base ISA only) ------------------------------
__device__ __forceinline__ uint32_t smem_u32(const void* p) {
    uint32_t a;
    asm("{ .reg .u64 t; cvta.to.shared.u64 t, %1; cvt.u32.u64 %0, t; }" : "=r"(a) : "l"(p));
    return a;
}
__device__ __forceinline__ void cp16(uint32_t dst, const void* src) {
    asm volatile("cp.async.cg.shared.global [%0], [%1], 16;" :: "r"(dst), "l"(src) : "memory");
}
__device__ __forceinline__ void cp_commit() {
    asm volatile("cp.async.commit_group;" ::: "memory");
}
__device__ __forceinline__ void cp_wait0() {
    asm volatile("cp.async.wait_group 0;" ::: "memory");
}
__device__ __forceinline__ void cp_wait1() {
    asm volatile("cp.async.wait_group 1;" ::: "memory");
}
__device__ __forceinline__ void ldm_x4(uint32_t* r, uint32_t addr) {
    asm volatile("ldmatrix.sync.aligned.m8n8.x4.shared.b16 {%0,%1,%2,%3}, [%4];"
                 : "=r"(r[0]), "=r"(r[1]), "=r"(r[2]), "=r"(r[3]) : "r"(addr));
}
__device__ __forceinline__ void mma16816(float* c, const uint32_t* a, const uint32_t* b) {
    asm volatile(
        "mma.sync.aligned.m16n8k16.row.col.f32.f16.f16.f32 "
        "{%0,%1,%2,%3}, {%4,%5,%6,%7}, {%8,%9}, {%0,%1,%2,%3};"
        : "+f"(c[0]), "+f"(c[1]), "+f"(c[2]), "+f"(c[3])
        : "r"(a[0]), "r"(a[1]), "r"(a[2]), "r"(a[3]), "r"(b[0]), "r"(b[1]));
}

__device__ __forceinline__ void split2(float x, __half& h, __half& l) {
    h = __float2half_rn(x);
    l = __float2half_rn(x - __half2float(h));
}
__device__ __forceinline__ float tanh_fast(float x) {
    return __fdividef(2.0f, __expf(-2.0f * x) + 1.0f) - 1.0f;
}

// ---------------- conversion kernels ---------------------------------------
__global__ void split_kernel(const float* __restrict__ src, int n, int hid, int lid) {
    __half* h = (__half*)sp(hid);
    __half* l = (__half*)sp(lid);
    int i = (blockIdx.x * blockDim.x + threadIdx.x) * 4;
    if (i + 3 < n) {
        float4 v = *(const float4*)(src + i);
        __half h0, l0, h1, l1, h2, l2, h3, l3;
        split2(v.x, h0, l0); split2(v.y, h1, l1);
        split2(v.z, h2, l2); split2(v.w, h3, l3);
        *(__half2*)(h + i)     = __halves2half2(h0, h1);
        *(__half2*)(h + i + 2) = __halves2half2(h2, h3);
        *(__half2*)(l + i)     = __halves2half2(l0, l1);
        *(__half2*)(l + i + 2) = __halves2half2(l2, l3);
    }
}

// All five weight transposes in ONE launch.
struct TAll {
    const float* W[5];
    int K[5], N[5], hid[5], lid[5], base[5], nbx[5];
};

__global__ void transpose_all(TAll p) {
    __shared__ float t[64][65];
    const int b = blockIdx.x;
    int i;
    if      (b >= p.base[4]) i = 4;
    else if (b >= p.base[3]) i = 3;
    else if (b >= p.base[2]) i = 2;
    else if (b >= p.base[1]) i = 1;
    else                     i = 0;
    const int local = b - p.base[i];
    const int n0 = (local % p.nbx[i]) * 64;
    const int k0 = (local / p.nbx[i]) * 64;
    const float* W = p.W[i];
    const int K = p.K[i], N = p.N[i];
    __half* oh = (__half*)sp(p.hid[i]);
    const int lid = p.lid[i];

    const int tx = threadIdx.x;
    const int ty = threadIdx.y;
#pragma unroll
    for (int j = 0; j < 64; j += 8)
        t[ty + j][tx] = W[(size_t)(k0 + ty + j) * N + n0 + tx];
    __syncthreads();
    if (lid >= 0) {
        __half* ol = (__half*)sp(lid);
#pragma unroll
        for (int j = 0; j < 64; j += 8) {
            int r = ty + j;
            size_t o = (size_t)(n0 + r) * K + k0 + tx;
            split2(t[tx][r], oh[o], ol[o]);
        }
    } else {
#pragma unroll
        for (int j = 0; j < 64; j += 8) {
            int r = ty + j;
            oh[(size_t)(n0 + r) * K + k0 + tx] = __float2half_rn(t[tx][r]);
        }
    }
}

// Wexp[256][1024][32] fp32 -> out[n*32+a][1024] fp16 (hi only).
__global__ void wexp_split64(const float* __restrict__ W, int hid) {
    __shared__ float t[64][33];
    __half* oh = (__half*)sp(hid);
    const int k0 = blockIdx.x * 64, n = blockIdx.y;
    const int tx = threadIdx.x;
    const int ty = threadIdx.y;
#pragma unroll
    for (int j = 0; j < 64; j += 16)
        t[ty + j][tx] = W[((size_t)n * 1024 + k0 + ty + j) * 32 + tx];
    __syncthreads();
    const int id = ty * 32 + tx;
    const int c = id & 63;
    const int r0 = id >> 6;
#pragma unroll
    for (int a = r0; a < 32; a += 8)
        oh[(size_t)(n * 32 + a) * 1024 + k0 + c] = __float2half_rn(t[c][a]);
}

// ---------------- generic warp-MMA GEMM (256 thr, 128x128) ------------------
template <int TA, int TB, int STAGES>
struct GemmCfg {
    static constexpr int STAGE = (TA + TB) * 16384;
    static constexpr int SMEM = 1024 + STAGES * STAGE;
    static constexpr int MINB = (SMEM <= 102400) ? 2 : 1;
};

template <int EPI, int TA, int TB, int STAGES>
__global__ void __launch_bounds__(256, GemmCfg<TA, TB, STAGES>::MINB)
mma_gemm(int ahi, int alo, int bhi, int blo,
         const float* __restrict__ bias,
         int o1, int o2, int M, int N, int K)
{
    constexpr int STAGE = GemmCfg<TA, TB, STAGES>::STAGE;
    constexpr uint32_t AL_OFF = 16384;
    constexpr uint32_t BH_OFF = TA * 16384;
    constexpr uint32_t BL_OFF = BH_OFF + 16384;

    extern __shared__ char smem_raw[];
    const uint32_t sb = (smem_u32(smem_raw) + 1023) & ~1023u;

    const __half* Ah = (const __half*)sp(ahi);
    const __half* Al = (const __half*)sp(alo);
    const __half* Bh = (const __half*)sp(bhi);
    const __half* Bl = (const __half*)sp(blo);

    const int tid = threadIdx.x;
    const int lane = tid & 31;
    const int wid = tid >> 5;
    const int wm = wid >> 2;
    const int wn = wid & 3;
    const int m0 = blockIdx.y * 128;
    const int n0 = blockIdx.x * 128;

    float acc[4][4][4];
#pragma unroll
    for (int i = 0; i < 4; i++)
#pragma unroll
        for (int j = 0; j < 4; j++)
#pragma unroll
            for (int q = 0; q < 4; q++) acc[i][j][q] = 0.f;

    const int C = K >> 6;

    auto issue = [&](int c, int s) {
        const uint32_t st = sb + s * STAGE;
        const int k0 = c * 64;
#pragma unroll
        for (int i = tid; i < 1024; i += 256) {
            int r = i >> 3, seg = i & 7;
            uint32_t off = SWZ((uint32_t)(r * 128 + seg * 16));
            size_t ga = (size_t)(m0 + r) * K + k0 + seg * 8;
            size_t gb = (size_t)(n0 + r) * K + k0 + seg * 8;
            cp16(st + off, Ah + ga);
            if (TA == 2) cp16(st + AL_OFF + off, Al + ga);
            cp16(st + BH_OFF + off, Bh + gb);
            if (TB == 2) cp16(st + BL_OFF + off, Bl + gb);
        }
        cp_commit();
    };

    const int quad = lane >> 3, qi = lane & 7;

    auto compute = [&](int s) {
        const uint32_t st = sb + s * STAGE;
#pragma unroll
        for (int kk = 0; kk < 4; kk++) {
            uint32_t ah[4][4], al[4][4];
#pragma unroll
            for (int mt = 0; mt < 4; mt++) {
                int row = wm * 64 + mt * 16 + (quad & 1) * 8 + qi;
                int colb = (kk * 16 + (quad >> 1) * 8) * 2;
                uint32_t ad = st + SWZ((uint32_t)(row * 128 + colb));
                ldm_x4(ah[mt], ad);
                if (TA == 2) ldm_x4(al[mt], ad + AL_OFF);
            }
            uint32_t bh[4][2], bl[4][2];
#pragma unroll
            for (int p = 0; p < 2; p++) {
                int row = wn * 32 + p * 16 + (quad >> 1) * 8 + qi;
                int colb = (kk * 16 + (quad & 1) * 8) * 2;
                uint32_t bd = st + BH_OFF + SWZ((uint32_t)(row * 128 + colb));
                uint32_t r4[4];
                ldm_x4(r4, bd);
                bh[p * 2][0] = r4[0]; bh[p * 2][1] = r4[1];
                bh[p * 2 + 1][0] = r4[2]; bh[p * 2 + 1][1] = r4[3];
                if (TB == 2) {
                    ldm_x4(r4, bd + 16384);
                    bl[p * 2][0] = r4[0]; bl[p * 2][1] = r4[1];
                    bl[p * 2 + 1][0] = r4[2]; bl[p * 2 + 1][1] = r4[3];
                }
            }
#pragma unroll
            for (int mt = 0; mt < 4; mt++)
#pragma unroll
                for (int nt = 0; nt < 4; nt++) {
                    mma16816(acc[mt][nt], ah[mt], bh[nt]);
                    if (TB == 2) mma16816(acc[mt][nt], ah[mt], bl[nt]);
                    if (TA == 2) mma16816(acc[mt][nt], al[mt], bh[nt]);
                }
        }
    };

    if constexpr (STAGES == 3) {
        issue(0, 0);
        if (C > 1) issue(1, 1);
        for (int c = 0; c < C; ++c) {
            if (c + 1 < C) cp_wait1();
            else           cp_wait0();
            __syncthreads();
            compute(c % 3);
            if (c + 2 < C) issue(c + 2, (c + 2) % 3);
        }
    } else {
        issue(0, 0);
        for (int c = 0; c < C; ++c) {
            if (c + 1 < C) { issue(c + 1, (c + 1) & 1); cp_wait1(); }
            else           { cp_wait0(); }
            __syncthreads();
            compute(c & 1);
            __syncthreads();
        }
    }

    const int r4 = lane >> 2;
    const int cp2 = (lane & 3) * 2;

    if constexpr (EPI == 1) {
        float* o = (float*)sp(o1);
#pragma unroll
        for (int mt = 0; mt < 4; mt++)
#pragma unroll
            for (int nt = 0; nt < 4; nt++) {
                int row = m0 + wm * 64 + mt * 16 + r4;
                int col = n0 + wn * 32 + nt * 8 + cp2;
                float2 v0 = {acc[mt][nt][0] + bias[col], acc[mt][nt][1] + bias[col + 1]};
                float2 v1 = {acc[mt][nt][2] + bias[col], acc[mt][nt][3] + bias[col + 1]};
                *(float2*)(o + (size_t)row * N + col) = v0;
                *(float2*)(o + (size_t)(row + 8) * N + col) = v1;
            }
    } else {
        __half* oh = (__half*)sp(o1);
        __half* ol = (__half*)sp(o2);
#pragma unroll
        for (int mt = 0; mt < 4; mt++)
#pragma unroll
            for (int nt = 0; nt < 4; nt++) {
                int row = m0 + wm * 64 + mt * 16 + r4;
                int col = n0 + wn * 32 + nt * 8 + cp2;
                float b0 = bias[col], b1 = bias[col + 1];
#pragma unroll
                for (int h = 0; h < 2; h++) {
                    int rr = row + h * 8;
                    float y0 = fmaxf(acc[mt][nt][h * 2 + 0] + b0, 0.f);
                    float y1 = fmaxf(acc[mt][nt][h * 2 + 1] + b1, 0.f);
                    __half h0, l0, h1, l1;
                    split2(y0, h0, l0);
                    split2(y1, h1, l1);
                    *(__half2*)(oh + (size_t)rr * N + col) = __halves2half2(h0, h1);
                    *(__half2*)(ol + (size_t)rr * N + col) = __halves2half2(l0, l1);
                }
            }
    }
}

// ---------------- merged L1+loc GEMM (3-term, single-buffered, 2 CTA/SM) ----
static constexpr int DUAL_STAGE = 4 * 16384;
static constexpr int DUAL_SMEM = 1024 + DUAL_STAGE;

__global__ void __launch_bounds__(256, 2)
mma_dual(int ahi, int alo,
         int b1h, int b1l, const float* __restrict__ bias1, int o1h, int o1l,
         int b2h, int b2l, const float* __restrict__ bias2, int o2h, int o2l,
         int M, int K)
{
    constexpr uint32_t AL_OFF = 16384, BH_OFF = 32768, BL_OFF = 49152;

    extern __shared__ char smem_raw[];
    const uint32_t sb = (smem_u32(smem_raw) + 1023) & ~1023u;

    const int n0g = blockIdx.x * 128;
    const bool sec = (n0g >= 1024);
    const int nb0 = sec ? n0g - 1024 : n0g;

    const __half* Ah = (const __half*)sp(ahi);
    const __half* Al = (const __half*)sp(alo);
    const __half* Bh = (const __half*)sp(sec ? b2h : b1h);
    const __half* Bl = (const __half*)sp(sec ? b2l : b1l);
    const float* bias = sec ? bias2 : bias1;
    __half* oh = (__half*)sp(sec ? o2h : o1h);
    __half* ol = (__half*)sp(sec ? o2l : o1l);

    const int tid = threadIdx.x;
    const int lane = tid & 31;
    const int wid = tid >> 5;
    const int wm = wid >> 2;
    const int wn = wid & 3;
    const int m0 = blockIdx.y * 128;

    float acc[4][4][4];
#pragma unroll
    for (int i = 0; i < 4; i++)
#pragma unroll
        for (int j = 0; j < 4; j++)
#pragma unroll
            for (int q = 0; q < 4; q++) acc[i][j][q] = 0.f;

    const int C = K >> 6;

    auto issue = [&](int c) {
        const uint32_t st = sb;
        const int k0 = c * 64;
#pragma unroll
        for (int i = tid; i < 1024; i += 256) {
            int r = i >> 3, seg = i & 7;
            uint32_t off = SWZ((uint32_t)(r * 128 + seg * 16));
            size_t ga = (size_t)(m0 + r) * K + k0 + seg * 8;
            size_t gb = (size_t)(nb0 + r) * K + k0 + seg * 8;
            cp16(st + off, Ah + ga);
            cp16(st + AL_OFF + off, Al + ga);
            cp16(st + BH_OFF + off, Bh + gb);
            cp16(st + BL_OFF + off, Bl + gb);
        }
        cp_commit();
    };

    const int quad = lane >> 3, qi = lane & 7;

    auto compute = [&]() {
        const uint32_t st = sb;
#pragma unroll
        for (int kk = 0; kk < 4; kk++) {
            uint32_t ah[4][4], al[4][4];
#pragma unroll
            for (int mt = 0; mt < 4; mt++) {
                int row = wm * 64 + mt * 16 + (quad & 1) * 8 + qi;
                int colb = (kk * 16 + (quad >> 1) * 8) * 2;
                uint32_t ad = st + SWZ((uint32_t)(row * 128 + colb));
                ldm_x4(ah[mt], ad);
                ldm_x4(al[mt], ad + AL_OFF);
            }
            uint32_t bh[4][2], bl[4][2];
#pragma unroll
            for (int p = 0; p < 2; p++) {
                int row = wn * 32 + p * 16 + (quad >> 1) * 8 + qi;
                int colb = (kk * 16 + (quad & 1) * 8) * 2;
                uint32_t bd = st + BH_OFF + SWZ((uint32_t)(row * 128 + colb));
                uint32_t r4[4];
                ldm_x4(r4, bd);
                bh[p * 2][0] = r4[0]; bh[p * 2][1] = r4[1];
                bh[p * 2 + 1][0] = r4[2]; bh[p * 2 + 1][1] = r4[3];
                ldm_x4(r4, bd + 16384);
                bl[p * 2][0] = r4[0]; bl[p * 2][1] = r4[1];
                bl[p * 2 + 1][0] = r4[2]; bl[p * 2 + 1][1] = r4[3];
            }
#pragma unroll
            for (int mt = 0; mt < 4; mt++)
#pragma unroll
                for (int nt = 0; nt < 4; nt++) {
                    mma16816(acc[mt][nt], ah[mt], bh[nt]);
                    mma16816(acc[mt][nt], ah[mt], bl[nt]);
                    mma16816(acc[mt][nt], al[mt], bh[nt]);
                }
        }
    };

    for (int c = 0; c < C; ++c) {
        issue(c);
        cp_wait0();
        __syncthreads();
        compute();
        __syncthreads();
    }

    const int r4 = lane >> 2;
    const int cp2 = (lane & 3) * 2;
#pragma unroll
    for (int mt = 0; mt < 4; mt++)
#pragma unroll
        for (int nt = 0; nt < 4; nt++) {
            int row = m0 + wm * 64 + mt * 16 + r4;
            int col = nb0 + wn * 32 + nt * 8 + cp2;
            float b0 = bias[col], b1 = bias[col + 1];
#pragma unroll
            for (int h = 0; h < 2; h++) {
                int rr = row + h * 8;
                float y0 = fmaxf(acc[mt][nt][h * 2 + 0] + b0, 0.f);
                float y1 = fmaxf(acc[mt][nt][h * 2 + 1] + b1, 0.f);
                __half h0, l0, h1, l1;
                split2(y0, h0, l0);
                split2(y1, h1, l1);
                *(__half2*)(oh + (size_t)rr * 1024 + col) = __halves2half2(h0, h1);
                *(__half2*)(ol + (size_t)rr * 1024 + col) = __halves2half2(l0, l1);
            }
        }
}

// ---------------- wide expert GEMM (1-term, 128x256, 3-stage, 1 sync) -------
static constexpr int EXP_STAGE = 49152;
static constexpr int EXP_SMEM = 1024 + 3 * EXP_STAGE;
static constexpr uint32_t EXP_B_OFF = 16384;

__global__ void __launch_bounds__(512, 1)
mma_exp(int ahi, int bhi,
        const float* __restrict__ bexp, const float* __restrict__ act,
        int o1, int K)
{
    extern __shared__ char smem_raw[];
    const uint32_t sb = (smem_u32(smem_raw) + 1023) & ~1023u;

    const __half* Ah = (const __half*)sp(ahi);
    const __half* Bh = (const __half*)sp(bhi);

    const int tid = threadIdx.x;
    const int lane = tid & 31;
    const int wid = tid >> 5;
    const int wm = wid >> 3;
    const int wn = wid & 7;
    const int m0 = blockIdx.y * 128;
    const int n0 = blockIdx.x * 256;

    float acc[4][4][4];
#pragma unroll
    for (int i = 0; i < 4; i++)
#pragma unroll
        for (int j = 0; j < 4; j++)
#pragma unroll
            for (int q = 0; q < 4; q++) acc[i][j][q] = 0.f;

    const int C = K >> 6;

    auto issue = [&](int c, int s) {
        const uint32_t st = sb + s * EXP_STAGE;
        const int k0 = c * 64;
#pragma unroll
        for (int i = tid; i < 1024; i += 512) {
            int r = i >> 3, seg = i & 7;
            uint32_t off = SWZ((uint32_t)(r * 128 + seg * 16));
            cp16(st + off, Ah + (size_t)(m0 + r) * K + k0 + seg * 8);
        }
#pragma unroll
        for (int i = tid; i < 2048; i += 512) {
            int r = i >> 3, seg = i & 7;
            uint32_t off = SWZ((uint32_t)(r * 128 + seg * 16));
            cp16(st + EXP_B_OFF + off, Bh + (size_t)(n0 + r) * K + k0 + seg * 8);
        }
        cp_commit();
    };

    const int quad = lane >> 3, qi = lane & 7;

    auto compute = [&](int s) {
        const uint32_t st = sb + s * EXP_STAGE;
#pragma unroll
        for (int kk = 0; kk < 4; kk++) {
            uint32_t ah[4][4];
#pragma unroll
            for (int mt = 0; mt < 4; mt++) {
                int row = wm * 64 + mt * 16 + (quad & 1) * 8 + qi;
                int colb = (kk * 16 + (quad >> 1) * 8) * 2;
                ldm_x4(ah[mt], st + SWZ((uint32_t)(row * 128 + colb)));
            }
            uint32_t bh[4][2];
#pragma unroll
            for (int p = 0; p < 2; p++) {
                int row = wn * 32 + p * 16 + (quad >> 1) * 8 + qi;
                int colb = (kk * 16 + (quad & 1) * 8) * 2;
                uint32_t r4[4];
                ldm_x4(r4, st + EXP_B_OFF + SWZ((uint32_t)(row * 128 + colb)));
                bh[p * 2][0] = r4[0]; bh[p * 2][1] = r4[1];
                bh[p * 2 + 1][0] = r4[2]; bh[p * 2 + 1][1] = r4[3];
            }
#pragma unroll
            for (int mt = 0; mt < 4; mt++)
#pragma unroll
                for (int nt = 0; nt < 4; nt++)
                    mma16816(acc[mt][nt], ah[mt], bh[nt]);
        }
    };

    issue(0, 0);
    issue(1, 1);
    for (int c = 0; c < C; ++c) {
        if (c + 1 < C) cp_wait1();
        else           cp_wait0();
        __syncthreads();
        compute(c % 3);
        if (c + 2 < C) issue(c + 2, (c + 2) % 3);
    }

    const int r4 = lane >> 2;
    const int cp2 = (lane & 3) * 2;
    float* dist = (float*)sp(o1);
    const int nc = blockIdx.x * 8 + wn;
#pragma unroll
    for (int mt = 0; mt < 4; mt++) {
#pragma unroll
        for (int h = 0; h < 2; h++) {
            int row = m0 + wm * 64 + mt * 16 + r4 + h * 8;
            float ss = 0.f;
#pragma unroll
            for (int nt = 0; nt < 4; nt++) {
                int col = n0 + wn * 32 + nt * 8 + cp2;
                int ai = nt * 8 + cp2;
                float z0 = acc[mt][nt][h * 2 + 0] + bexp[col];
                float z1 = acc[mt][nt][h * 2 + 1] + bexp[col + 1];
                float d0 = tanh_fast(z0) - act[(size_t)row * 32 + ai];
                float d1 = tanh_fast(z1) - act[(size_t)row * 32 + ai + 1];
                ss += d0 * d0 + d1 * d1;
            }
            ss += __shfl_xor_sync(0xffffffffu, ss, 1);
            ss += __shfl_xor_sync(0xffffffffu, ss, 2);
            if ((lane & 3) == 0)
                dist[(size_t)row * 256 + nc] = sqrtf(ss + 0.01f);
        }
    }
}

// ---------------- finalize: softmax(-dist) . values ------------------------
__global__ void finalize_kernel(float* __restrict__ out) {
    const float* dist = (const float*)sp(19);
    const float* values = (const float*)sp(18);
    const int b = blockIdx.x;
    const int n = threadIdx.x;
    const int lane = n & 31, w = n >> 5;

    float logit = -dist[(size_t)b * 256 + n];
    float v = values[(size_t)b * 256 + n];

    __shared__ float smax[8], s_e[8], s_ev[8];
    float mx = logit;
#pragma unroll
    for (int off = 16; off; off >>= 1)
        mx = fmaxf(mx, __shfl_xor_sync(0xffffffffu, mx, off));
    if (lane == 0) smax[w] = mx;
    __syncthreads();
    float bm = smax[0];
#pragma unroll
    for (int i = 1; i < 8; i++) bm = fmaxf(bm, smax[i]);

    float e = expf(logit - bm);
    float se = e, sev = e * v;
#pragma unroll
    for (int off = 16; off; off >>= 1) {
        se += __shfl_xor_sync(0xffffffffu, se, off);
        sev += __shfl_xor_sync(0xffffffffu, sev, off);
    }
    if (lane == 0) { s_e[w] = se; s_ev[w] = sev; }
    __syncthreads();
    if (n == 0) {
        float te = 0.f, tev = 0.f;
#pragma unroll
        for (int i = 0; i < 8; i++) { te += s_e[i]; tev += s_ev[i]; }
        out[b] = tev / te;
    }
}

// ---------------- launch ----------------------------------------------------
extern "C" void kernel_launch(void* const* d_in, const int* in_sizes, int n_in,
                              void* d_out, int out_size)
{
    const float* s    = (const float*)d_in[0];
    const float* act  = (const float*)d_in[1];
    const float* Wv1  = (const float*)d_in[2];
    const float* bv1  = (const float*)d_in[3];
    const float* Wv2  = (const float*)d_in[4];
    const float* bv2  = (const float*)d_in[5];
    const float* Wv3  = (const float*)d_in[6];
    const float* bv3  = (const float*)d_in[7];
    const float* Wv4  = (const float*)d_in[8];
    const float* bv4  = (const float*)d_in[9];
    const float* Wl1  = (const float*)d_in[10];
    const float* bl1  = (const float*)d_in[11];
    const float* Wexp = (const float*)d_in[12];
    const float* bexp = (const float*)d_in[13];
    float* out = (float*)d_out;

    constexpr int S3 = GemmCfg<2, 2, 2>::SMEM;   // L4: 132KB, 1 CTA/SM
    constexpr int S1 = GemmCfg<1, 1, 3>::SMEM;   // L2/L3: 97KB, 2 CTAs/SM

    cudaFuncSetAttribute(mma_gemm<1,2,2,2>, cudaFuncAttributeMaxDynamicSharedMemorySize, S3);
    cudaFuncSetAttribute(mma_gemm<0,1,1,3>, cudaFuncAttributeMaxDynamicSharedMemorySize, S1);
    cudaFuncSetAttribute(mma_dual, cudaFuncAttributeMaxDynamicSharedMemorySize, DUAL_SMEM);
    cudaFuncSetAttribute(mma_exp, cudaFuncAttributeMaxDynamicSharedMemorySize, EXP_SMEM);

    // Side stream + fork/join events. Created fresh each call (kernel_launch
    // only runs for correctness + capture, never in the timed loop; the graph
    // replays these as captured nodes). No device memory involved.
    cudaStream_t sB;
    cudaStreamCreateWithFlags(&sB, cudaStreamNonBlocking);
    cudaEvent_t evFork, evJoin;
    cudaEventCreateWithFlags(&evFork, cudaEventDisableTiming);
    cudaEventCreateWithFlags(&evJoin, cudaEventDisableTiming);

    dim3 t64(64, 8);
    dim3 tw(32, 16);

    // conversions (main stream)
    split_kernel<<<512, 256>>>(s, 4096 * 128, 4, 5);

    TAll ta;
    ta.W[0] = Wv1;  ta.K[0] = 128;  ta.N[0] = 1024; ta.hid[0] = 6;  ta.lid[0] = 7;  ta.base[0] = 0;   ta.nbx[0] = 16;
    ta.W[1] = Wv2;  ta.K[1] = 1024; ta.N[1] = 1024; ta.hid[1] = 8;  ta.lid[1] = -1; ta.base[1] = 32;  ta.nbx[1] = 16;
    ta.W[2] = Wv3;  ta.K[2] = 1024; ta.N[2] = 1024; ta.hid[2] = 10; ta.lid[2] = -1; ta.base[2] = 288; ta.nbx[2] = 16;
    ta.W[3] = Wv4;  ta.K[3] = 1024; ta.N[3] = 256;  ta.hid[3] = 12; ta.lid[3] = 13; ta.base[3] = 544; ta.nbx[3] = 4;
    ta.W[4] = Wl1;  ta.K[4] = 128;  ta.N[4] = 1024; ta.hid[4] = 14; ta.lid[4] = 15; ta.base[4] = 608; ta.nbx[4] = 16;
    transpose_all<<<640, t64>>>(ta);

    wexp_split64<<<dim3(16, 256), tw>>>(Wexp, 16);

    // merged L1 + location (3-term): a0 = relu(s@Wv1), a1 = relu(s@Wl1)
    mma_dual<<<dim3(16, 32), 256, DUAL_SMEM>>>(4, 5,
                                               6, 7,  bv1, 0, 1,
                                               14, 15, bl1, 2, 3,
                                               4096, 128);

    // ---- fork: expert on side stream, value chain on main stream ----------
    cudaEventRecord(evFork, 0);
    cudaStreamWaitEvent(sB, evFork, 0);

    // expert GEMM + fused tanh/dist (reads a1 + weh; writes dist)
    mma_exp<<<dim3(32, 32), 512, EXP_SMEM, sB>>>(2, 16, bexp, act, 19, 1024);
    cudaEventRecord(evJoin, sB);

    // L2 (1-term): a0 -> wel planes (17, 20) — NOT a1 (expert reads it)
    mma_gemm<0,1,1,3><<<dim3(8, 32), 256, S1>>>(0, 1, 8, 9,   bv2, 17, 20, 4096, 1024, 1024);
    // L3 (1-term): wel planes -> a0
    mma_gemm<0,1,1,3><<<dim3(8, 32), 256, S1>>>(17, 20, 10, 11, bv3, 0, 1, 4096, 1024, 1024);
    // L4 (3-term): a0 -> values
    mma_gemm<1,2,2,2><<<dim3(2, 32), 256, S3>>>(0, 1, 12, 13, bv4, 18, 0, 4096, 256, 1024);

    // ---- join: finalize needs both dist (sB) and values (main) ------------
    cudaStreamWaitEvent(0, evJoin, 0);
    finalize_kernel<<<4096, 256>>>(out);
}